// round 5
// baseline (speedup 1.0000x reference)
#include <cuda_runtime.h>
#include <cuda_bf16.h>
#include <cstdint>

// Problem constants
#define BLROWS 4096   // B*L = 2*2048
#define LSEQ   2048
#define DMODEL 1024
#define DINNER 2048
#define DSTATE 16
#define DTRANK 64

typedef __nv_bfloat16 bf16;

// ---------------------------------------------------------------------------
// Scratch (device globals)
// ---------------------------------------------------------------------------
__device__ bf16  g_xh [(size_t)BLROWS * DMODEL];
__device__ bf16  g_xl [(size_t)BLROWS * DMODEL];
__device__ bf16  g_xsh[(size_t)BLROWS * DINNER];
__device__ bf16  g_xsl[(size_t)BLROWS * DINNER];
__device__ float g_sres[(size_t)BLROWS * DINNER];
__device__ float g_u  [(size_t)BLROWS * DINNER];
__device__ float g_dbc[(size_t)BLROWS * 96];
__device__ bf16  g_dth[(size_t)BLROWS * DTRANK];
__device__ bf16  g_dtl[(size_t)BLROWS * DTRANK];
__device__ float g_delta[(size_t)BLROWS * DINNER];
__device__ bf16  g_yh [(size_t)BLROWS * DINNER];
__device__ bf16  g_yl [(size_t)BLROWS * DINNER];
// Pre-split transposed weights ([N,K] K-major)
__device__ bf16  g_WinTh [(size_t)4096 * 1024],  g_WinTl [(size_t)4096 * 1024];
__device__ bf16  g_convTh[(size_t)4 * 2048 * 1024], g_convTl[(size_t)4 * 2048 * 1024];
__device__ bf16  g_WoutTh[(size_t)1024 * 2048], g_WoutTl[(size_t)1024 * 2048];
__device__ bf16  g_WdtTh [(size_t)2048 * 64],   g_WdtTl [(size_t)2048 * 64];

// ---------------------------------------------------------------------------
// PTX helpers
// ---------------------------------------------------------------------------
__device__ __forceinline__ uint32_t smem_u32(const void* p) {
    uint32_t a;
    asm("{ .reg .u64 t; cvta.to.shared.u64 t, %1; cvt.u32.u64 %0, t; }"
        : "=r"(a) : "l"(p));
    return a;
}
__device__ __forceinline__ void ldsm4(uint32_t* r, uint32_t addr) {
    asm volatile("ldmatrix.sync.aligned.m8n8.x4.shared.b16 {%0,%1,%2,%3}, [%4];"
        : "=r"(r[0]), "=r"(r[1]), "=r"(r[2]), "=r"(r[3]) : "r"(addr));
}
__device__ __forceinline__ void mma16816(
    float& d0, float& d1, float& d2, float& d3,
    uint32_t a0, uint32_t a1, uint32_t a2, uint32_t a3,
    uint32_t b0, uint32_t b1)
{
    asm volatile(
        "mma.sync.aligned.m16n8k16.row.col.f32.bf16.bf16.f32 "
        "{%0,%1,%2,%3}, {%4,%5,%6,%7}, {%8,%9}, {%0,%1,%2,%3};"
        : "+f"(d0), "+f"(d1), "+f"(d2), "+f"(d3)
        : "r"(a0), "r"(a1), "r"(a2), "r"(a3), "r"(b0), "r"(b1));
}
// bf16 2-way split of two floats -> packed bf16x2 (hi, lo)
__device__ __forceinline__ void split2(float x, float y, uint32_t& hi, uint32_t& lo) {
    bf16 hx = __float2bfloat16_rn(x);
    bf16 hy = __float2bfloat16_rn(y);
    __nv_bfloat162 h; h.x = hx; h.y = hy;
    __nv_bfloat162 l = __floats2bfloat162_rn(x - __bfloat162float(hx),
                                             y - __bfloat162float(hy));
    hi = *reinterpret_cast<uint32_t*>(&h);
    lo = *reinterpret_cast<uint32_t*>(&l);
}
// SMEM tile: 128 rows x 32 bf16 (64B/row, 4x16B chunks), xor-swizzled
__device__ __forceinline__ uint32_t swz(int row, int chunk) {
    return (uint32_t)((row << 6) + (((chunk ^ ((row >> 1) & 3)) & 3) << 4));
}
__device__ __forceinline__ float silu(float v) { return v / (1.f + __expf(-v)); }

// ---------------------------------------------------------------------------
// bf16x3 mma GEMM.  Pre-split operands, LDG->reg->STS double-buffer pipeline,
// ONE __syncthreads per k-iter.  C-tile[128,128] = A[M,K] @ Bt[N,K]^T.
// NTAPS=4: grouped causal conv.  EPI: 0 fp32 store; 1 softplus+clip(+bias);
// 2 bias+silu; 3 GEMM1 dual output.
// ---------------------------------------------------------------------------
template <int NTAPS, int EPI>
__global__ __launch_bounds__(256) void mma_gemm3(
    const bf16* __restrict__ Ah, const bf16* __restrict__ Al, int lda,
    const bf16* __restrict__ Bh, const bf16* __restrict__ Bl,
    long tap_stride, int ldb,
    float* __restrict__ C, int ldc, int K, const float* __restrict__ bias,
    bf16* __restrict__ xsh, bf16* __restrict__ xsl)
{
    extern __shared__ char dyn[];
    const uint32_t rawb = smem_u32(dyn);
    const uint32_t base = (rawb + 1023u) & ~1023u;
    char* tp = dyn + (base - rawb);

    const int tid  = threadIdx.x;
    const int lane = tid & 31;
    const int wid  = tid >> 5;
    const int wm   = wid & 1;
    const int wn   = wid >> 1;
    const int m0   = blockIdx.y * 128;
    const int n0   = blockIdx.x * 128;
    const int colbase = (NTAPS == 4 && n0 >= 1024) ? 1024 : 0;
    const int NKB = K >> 5;
    const int TOT = NTAPS * NKB;

    const int a_r  = lane & 15;
    const int a_cx = lane >> 4;
    const int b_r  = (lane & 7) + ((lane >> 4) << 3);
    const int b_cx = (lane >> 3) & 1;

    // per-thread chunk coords (2 chunks of 16B per subtile)
    const int row0 = tid >> 2,        seg0 = tid & 3;
    const int row1 = (tid + 256) >> 2, seg1 = (tid + 256) & 3;
    const uint32_t so0 = swz(row0, seg0), so1 = swz(row1, seg1);

    float acc[4][4][4];
#pragma unroll
    for (int i = 0; i < 4; i++)
#pragma unroll
        for (int j = 0; j < 4; j++)
#pragma unroll
            for (int k = 0; k < 4; k++) acc[i][j][k] = 0.f;

    uint4 ra[2], rla[2], rb[2], rlb[2];

    auto loadregs = [&](int it) {
        int tap = (NTAPS == 1) ? 0 : (it >> 5);
        int kb  = (NTAPS == 1) ? it : (it & 31);
        const bf16* Bhw = Bh + (long)tap * tap_stride;
        const bf16* Blw = Bl + (long)tap * tap_stride;
#pragma unroll
        for (int i = 0; i < 2; i++) {
            int row = i ? row1 : row0;
            int seg = i ? seg1 : seg0;
            long off = (long)(kb * 32 + seg * 8);
            if (NTAPS == 4) {
                int t = m0 + row;
                bool ok = (t & (LSEQ - 1)) >= (3 - tap);
                long arow = t + tap - 3;
                if (ok) {
                    ra[i]  = *(const uint4*)(Ah + arow * lda + colbase + off);
                    rla[i] = *(const uint4*)(Al + arow * lda + colbase + off);
                } else {
                    ra[i]  = make_uint4(0, 0, 0, 0);
                    rla[i] = make_uint4(0, 0, 0, 0);
                }
            } else {
                long arow = m0 + row;
                ra[i]  = *(const uint4*)(Ah + arow * lda + off);
                rla[i] = *(const uint4*)(Al + arow * lda + off);
            }
            long brow = n0 + row;
            rb[i]  = *(const uint4*)(Bhw + brow * ldb + off);
            rlb[i] = *(const uint4*)(Blw + brow * ldb + off);
        }
    };

    auto stsregs = [&](int s) {
        char* sb = tp + s * 32768;
#pragma unroll
        for (int i = 0; i < 2; i++) {
            uint32_t so = i ? so1 : so0;
            *(uint4*)(sb + so)         = ra[i];
            *(uint4*)(sb + 8192 + so)  = rla[i];
            *(uint4*)(sb + 16384 + so) = rb[i];
            *(uint4*)(sb + 24576 + so) = rlb[i];
        }
    };

    auto mma_block = [&](int s) {
        uint32_t sb = base + (uint32_t)s * 32768u;
        uint32_t aHiB = sb, aLoB = sb + 8192, bHiB = sb + 16384, bLoB = sb + 24576;
#pragma unroll
        for (int ks = 0; ks < 2; ks++) {
            uint32_t a[4][4], bh[4][2], bx[4][2];
#pragma unroll
            for (int mf = 0; mf < 4; mf++) {
                int row = wm * 64 + mf * 16 + a_r;
                ldsm4(a[mf], aHiB + swz(row, ks * 2 + a_cx));
            }
#pragma unroll
            for (int p = 0; p < 2; p++) {
                int row = wn * 32 + p * 16 + b_r;
                uint32_t t[4];
                ldsm4(t, bHiB + swz(row, ks * 2 + b_cx));
                bh[p * 2][0] = t[0]; bh[p * 2][1] = t[1];
                bh[p * 2 + 1][0] = t[2]; bh[p * 2 + 1][1] = t[3];
            }
#pragma unroll
            for (int mf = 0; mf < 4; mf++)
#pragma unroll
                for (int nf = 0; nf < 4; nf++)
                    mma16816(acc[mf][nf][0], acc[mf][nf][1], acc[mf][nf][2], acc[mf][nf][3],
                             a[mf][0], a[mf][1], a[mf][2], a[mf][3], bh[nf][0], bh[nf][1]);
#pragma unroll
            for (int p = 0; p < 2; p++) {
                int row = wn * 32 + p * 16 + b_r;
                uint32_t t[4];
                ldsm4(t, bLoB + swz(row, ks * 2 + b_cx));
                bx[p * 2][0] = t[0]; bx[p * 2][1] = t[1];
                bx[p * 2 + 1][0] = t[2]; bx[p * 2 + 1][1] = t[3];
            }
#pragma unroll
            for (int mf = 0; mf < 4; mf++)
#pragma unroll
                for (int nf = 0; nf < 4; nf++)
                    mma16816(acc[mf][nf][0], acc[mf][nf][1], acc[mf][nf][2], acc[mf][nf][3],
                             a[mf][0], a[mf][1], a[mf][2], a[mf][3], bx[nf][0], bx[nf][1]);
#pragma unroll
            for (int mf = 0; mf < 4; mf++) {
                int row = wm * 64 + mf * 16 + a_r;
                ldsm4(a[mf], aLoB + swz(row, ks * 2 + a_cx));
            }
#pragma unroll
            for (int mf = 0; mf < 4; mf++)
#pragma unroll
                for (int nf = 0; nf < 4; nf++)
                    mma16816(acc[mf][nf][0], acc[mf][nf][1], acc[mf][nf][2], acc[mf][nf][3],
                             a[mf][0], a[mf][1], a[mf][2], a[mf][3], bh[nf][0], bh[nf][1]);
        }
    };

    // Pipeline: load(it+1) -> mma(it) -> sts(it+1) -> sync
    loadregs(0);
    stsregs(0);
    __syncthreads();
    for (int it = 0; it < TOT; it++) {
        if (it + 1 < TOT) loadregs(it + 1);
        mma_block(it & 1);
        if (it + 1 < TOT) {
            stsregs((it + 1) & 1);
            __syncthreads();
        }
    }

    // Epilogue
#pragma unroll
    for (int mf = 0; mf < 4; mf++) {
        int r = m0 + wm * 64 + mf * 16 + (lane >> 2);
#pragma unroll
        for (int nf = 0; nf < 4; nf++) {
            int c = n0 + wn * 32 + nf * 8 + (lane & 3) * 2;
            float v0 = acc[mf][nf][0], v1 = acc[mf][nf][1];
            float v2 = acc[mf][nf][2], v3 = acc[mf][nf][3];
            if (EPI == 1) {
                float b0 = bias[c], b1 = bias[c + 1];
                float x0 = v0 + b0, x1 = v1 + b1, x2 = v2 + b0, x3 = v3 + b1;
                v0 = fminf(fmaxf(fmaxf(x0, 0.f) + log1pf(__expf(-fabsf(x0))), 1e-3f), 0.1f);
                v1 = fminf(fmaxf(fmaxf(x1, 0.f) + log1pf(__expf(-fabsf(x1))), 1e-3f), 0.1f);
                v2 = fminf(fmaxf(fmaxf(x2, 0.f) + log1pf(__expf(-fabsf(x2))), 1e-3f), 0.1f);
                v3 = fminf(fmaxf(fmaxf(x3, 0.f) + log1pf(__expf(-fabsf(x3))), 1e-3f), 0.1f);
            } else if (EPI == 2) {
                float b0 = bias[c], b1 = bias[c + 1];
                v0 = silu(v0 + b0); v1 = silu(v1 + b1);
                v2 = silu(v2 + b0); v3 = silu(v3 + b1);
            }
            if (EPI == 3) {
                if (n0 < 2048) {
                    uint32_t h, l;
                    split2(v0, v1, h, l);
                    *(uint32_t*)(xsh + (size_t)r * 2048 + c) = h;
                    *(uint32_t*)(xsl + (size_t)r * 2048 + c) = l;
                    split2(v2, v3, h, l);
                    *(uint32_t*)(xsh + (size_t)(r + 8) * 2048 + c) = h;
                    *(uint32_t*)(xsl + (size_t)(r + 8) * 2048 + c) = l;
                } else {
                    int cc = c - 2048;
                    *(float2*)(C + (size_t)r * ldc + cc)
                        = make_float2(silu(v0), silu(v1));
                    *(float2*)(C + (size_t)(r + 8) * ldc + cc)
                        = make_float2(silu(v2), silu(v3));
                }
            } else {
                *(float2*)(C + (size_t)r * ldc + c)       = make_float2(v0, v1);
                *(float2*)(C + (size_t)(r + 8) * ldc + c) = make_float2(v2, v3);
            }
        }
    }
}

// ---------------------------------------------------------------------------
// Transpose + split: src [R,C] fp32 -> dst_hi/lo [C,R] bf16
// ---------------------------------------------------------------------------
__global__ __launch_bounds__(256) void transpose_split(
    const float* __restrict__ src, bf16* __restrict__ dh, bf16* __restrict__ dl,
    int R, int C)
{
    __shared__ float t[32][33];
    int x = blockIdx.x * 32 + threadIdx.x;
#pragma unroll
    for (int j = 0; j < 4; j++) {
        int y = blockIdx.y * 32 + threadIdx.y + j * 8;
        t[threadIdx.y + j * 8][threadIdx.x] = src[(size_t)y * C + x];
    }
    __syncthreads();
    int x2 = blockIdx.y * 32 + threadIdx.x;
#pragma unroll
    for (int j = 0; j < 4; j++) {
        int y2 = blockIdx.x * 32 + threadIdx.y + j * 8;
        float v = t[threadIdx.x][threadIdx.y + j * 8];
        bf16 h = __float2bfloat16_rn(v);
        dh[(size_t)y2 * R + x2] = h;
        dl[(size_t)y2 * R + x2] = __float2bfloat16_rn(v - __bfloat162float(h));
    }
}

// ---------------------------------------------------------------------------
// Elementwise split: fp32[n] -> bf16 hi/lo
// ---------------------------------------------------------------------------
__global__ __launch_bounds__(256) void split_kernel(
    const float* __restrict__ src, bf16* __restrict__ dh, bf16* __restrict__ dl)
{
    size_t i = ((size_t)blockIdx.x * blockDim.x + threadIdx.x) * 4;
    float4 v = *(const float4*)(src + i);
    uint32_t h0, l0, h1, l1;
    split2(v.x, v.y, h0, l0);
    split2(v.z, v.w, h1, l1);
    *(uint2*)(dh + i) = make_uint2(h0, h1);
    *(uint2*)(dl + i) = make_uint2(l0, l1);
}

// Strided split: dt_raw = dbc[:, :64] -> dth/dtl [4096,64]
__global__ __launch_bounds__(256) void split_dt_kernel(
    const float* __restrict__ dbc, bf16* __restrict__ dh, bf16* __restrict__ dl)
{
    int i = blockIdx.x * blockDim.x + threadIdx.x;
    int row = i >> 5;
    int col = (i & 31) * 2;
    float v0 = dbc[(size_t)row * 96 + col];
    float v1 = dbc[(size_t)row * 96 + col + 1];
    uint32_t h, l;
    split2(v0, v1, h, l);
    *(uint32_t*)(dh + (size_t)row * 64 + col) = h;
    *(uint32_t*)(dl + (size_t)row * 64 + col) = l;
}

// ---------------------------------------------------------------------------
// Narrow GEMM: DBC[4096,96] = U @ W_x (fp32 SIMT)
// ---------------------------------------------------------------------------
__global__ __launch_bounds__(256) void gemm_n96_kernel(
    const float* __restrict__ A, const float* __restrict__ B, float* __restrict__ C)
{
    const int BK = 32, NN = 96;
    __shared__ float As[BK][32];
    __shared__ float Bs[BK][NN];

    const int m0 = blockIdx.x * 32;
    const int tid = threadIdx.x;
    const int tx = tid & 15;
    const int ty = tid >> 4;

    float acc[2][6];
#pragma unroll
    for (int r = 0; r < 2; r++)
#pragma unroll
        for (int j = 0; j < 6; j++) acc[r][j] = 0.f;

    for (int k0 = 0; k0 < DINNER; k0 += BK) {
        {
            int row = tid >> 3;
            int cv  = (tid & 7) * 4;
            float4 a = *(const float4*)(A + (size_t)(m0 + row) * DINNER + k0 + cv);
            As[cv + 0][row] = a.x; As[cv + 1][row] = a.y;
            As[cv + 2][row] = a.z; As[cv + 3][row] = a.w;
        }
#pragma unroll
        for (int i = 0; i < 3; i++) {
            int idx  = tid + i * 256;
            int rowB = idx / 24;
            int cv   = (idx % 24) * 4;
            *(float4*)(&Bs[rowB][cv]) =
                *(const float4*)(B + (size_t)(k0 + rowB) * NN + cv);
        }
        __syncthreads();
#pragma unroll
        for (int k = 0; k < BK; k++) {
            float a0 = As[k][ty * 2];
            float a1 = As[k][ty * 2 + 1];
#pragma unroll
            for (int j = 0; j < 6; j++) {
                float bb = Bs[k][tx * 6 + j];
                acc[0][j] = fmaf(a0, bb, acc[0][j]);
                acc[1][j] = fmaf(a1, bb, acc[1][j]);
            }
        }
        __syncthreads();
    }
#pragma unroll
    for (int r = 0; r < 2; r++) {
        int m = m0 + ty * 2 + r;
#pragma unroll
        for (int j = 0; j < 6; j++)
            C[(size_t)m * 96 + tx * 6 + j] = acc[r][j];
    }
}

// ---------------------------------------------------------------------------
// Selective scan, fused gate; writes gated y as bf16 hi/lo
// ---------------------------------------------------------------------------
__global__ __launch_bounds__(256) void scan_kernel(
    const float* __restrict__ delta, const float* __restrict__ u,
    const float* __restrict__ dbc, const float* __restrict__ A_log,
    const float* __restrict__ Dp, const float* __restrict__ sres,
    bf16* __restrict__ Yh, bf16* __restrict__ Yl)
{
    int tid = blockIdx.x * blockDim.x + threadIdx.x;
    int n = tid & 15;
    int d = (tid >> 4) & (DINNER - 1);
    int b = tid >> 15;

    const float a  = -__expf(A_log[d * DSTATE + n]);
    const float Dd = Dp[d];

    const size_t rowbase = (size_t)b * LSEQ;
    const float* dptr = delta + rowbase * DINNER + d;
    const float* uptr = u     + rowbase * DINNER + d;
    const float* bc   = dbc   + rowbase * 96;
    const float* rp   = sres  + rowbase * DINNER + d;
    bf16* yh = Yh + rowbase * DINNER + d;
    bf16* yl = Yl + rowbase * DINNER + d;

    float h = 0.f;
    for (int t = 0; t < LSEQ; t++) {
        float de = dptr[(size_t)t * DINNER];
        float uu = uptr[(size_t)t * DINNER];
        float Bn = bc[t * 96 + DTRANK + n];
        float Cn = bc[t * 96 + DTRANK + DSTATE + n];
        float dA = __expf(de * a);
        h = fmaf(dA, h, de * uu * Bn);
        float p = h * Cn;
        p += __shfl_xor_sync(0xffffffffu, p, 8);
        p += __shfl_xor_sync(0xffffffffu, p, 4);
        p += __shfl_xor_sync(0xffffffffu, p, 2);
        p += __shfl_xor_sync(0xffffffffu, p, 1);
        if (n == 0) {
            float yv = fmaf(uu, Dd, p) * rp[(size_t)t * DINNER];
            bf16 hh = __float2bfloat16_rn(yv);
            yh[(size_t)t * DINNER] = hh;
            yl[(size_t)t * DINNER] = __float2bfloat16_rn(yv - __bfloat162float(hh));
        }
    }
}

// ---------------------------------------------------------------------------
// Launch
// ---------------------------------------------------------------------------
static const int GEMM_SMEM = 2 * 32768 + 1024;

extern "C" void kernel_launch(void* const* d_in, const int* in_sizes, int n_in,
                              void* d_out, int out_size)
{
    (void)in_sizes; (void)n_in; (void)out_size;
    const float* x      = (const float*)d_in[0];
    const float* W_in   = (const float*)d_in[1];
    const float* conv_k = (const float*)d_in[2];
    const float* conv_b = (const float*)d_in[3];
    const float* W_x    = (const float*)d_in[4];
    const float* W_dt   = (const float*)d_in[5];
    const float* b_dt   = (const float*)d_in[6];
    const float* A_log  = (const float*)d_in[7];
    const float* Dvec   = (const float*)d_in[8];
    const float* W_out  = (const float*)d_in[9];
    float* out = (float*)d_out;

    bf16 *xh, *xl, *xsh, *xsl, *dth, *dtl, *yh, *yl;
    bf16 *winTh, *winTl, *convTh, *convTl, *woutTh, *woutTl, *wdtTh, *wdtTl;
    float *sres, *u, *dbc, *delta;
    cudaGetSymbolAddress((void**)&xh,   g_xh);   cudaGetSymbolAddress((void**)&xl,   g_xl);
    cudaGetSymbolAddress((void**)&xsh,  g_xsh);  cudaGetSymbolAddress((void**)&xsl,  g_xsl);
    cudaGetSymbolAddress((void**)&sres, g_sres); cudaGetSymbolAddress((void**)&u,    g_u);
    cudaGetSymbolAddress((void**)&dbc,  g_dbc);
    cudaGetSymbolAddress((void**)&dth,  g_dth);  cudaGetSymbolAddress((void**)&dtl,  g_dtl);
    cudaGetSymbolAddress((void**)&delta,g_delta);
    cudaGetSymbolAddress((void**)&yh,   g_yh);   cudaGetSymbolAddress((void**)&yl,   g_yl);
    cudaGetSymbolAddress((void**)&winTh, g_WinTh);  cudaGetSymbolAddress((void**)&winTl, g_WinTl);
    cudaGetSymbolAddress((void**)&convTh,g_convTh); cudaGetSymbolAddress((void**)&convTl,g_convTl);
    cudaGetSymbolAddress((void**)&woutTh,g_WoutTh); cudaGetSymbolAddress((void**)&woutTl,g_WoutTl);
    cudaGetSymbolAddress((void**)&wdtTh, g_WdtTh);  cudaGetSymbolAddress((void**)&wdtTl, g_WdtTl);

    cudaFuncSetAttribute(mma_gemm3<1, 3>, cudaFuncAttributeMaxDynamicSharedMemorySize, GEMM_SMEM);
    cudaFuncSetAttribute(mma_gemm3<4, 2>, cudaFuncAttributeMaxDynamicSharedMemorySize, GEMM_SMEM);
    cudaFuncSetAttribute(mma_gemm3<1, 1>, cudaFuncAttributeMaxDynamicSharedMemorySize, GEMM_SMEM);
    cudaFuncSetAttribute(mma_gemm3<1, 0>, cudaFuncAttributeMaxDynamicSharedMemorySize, GEMM_SMEM);

    // 0) weight transpose+split, activation split
    transpose_split<<<dim3(4096 / 32, 1024 / 32), dim3(32, 8)>>>(W_in, winTh, winTl, 1024, 4096);
    for (int w = 0; w < 4; w++)
        transpose_split<<<dim3(2048 / 32, 1024 / 32), dim3(32, 8)>>>(
            conv_k + (size_t)w * 1024 * 2048,
            convTh + (size_t)w * 2048 * 1024, convTl + (size_t)w * 2048 * 1024, 1024, 2048);
    transpose_split<<<dim3(1024 / 32, 2048 / 32), dim3(32, 8)>>>(W_out, woutTh, woutTl, 2048, 1024);
    transpose_split<<<dim3(2048 / 32, 64 / 32), dim3(32, 8)>>>(W_dt, wdtTh, wdtTl, 64, 2048);
    split_kernel<<<(BLROWS * DMODEL / 4) / 256, 256>>>(x, xh, xl);

    // 1) GEMM1: xs -> bf16 hi/lo, silu(res) -> sres fp32
    mma_gemm3<1, 3><<<dim3(32, 32), 256, GEMM_SMEM>>>(
        xh, xl, DMODEL, winTh, winTl, 0, DMODEL, sres, DINNER, DMODEL, nullptr, xsh, xsl);

    // 2) grouped causal conv (4 taps fused) + bias + silu -> u fp32
    mma_gemm3<4, 2><<<dim3(16, 32), 256, GEMM_SMEM>>>(
        xsh, xsl, DINNER, convTh, convTl, (long)2048 * 1024, 1024,
        u, DINNER, 1024, conv_b, nullptr, nullptr);

    // 3) dbc = u @ W_x (fp32 SIMT)
    gemm_n96_kernel<<<128, 256>>>(u, W_x, dbc);

    // 4) split dt_raw, delta GEMM (K=64) + softplus + clip
    split_dt_kernel<<<(BLROWS * 32) / 256, 256>>>(dbc, dth, dtl);
    mma_gemm3<1, 1><<<dim3(16, 32), 256, GEMM_SMEM>>>(
        dth, dtl, DTRANK, wdtTh, wdtTl, 0, DTRANK,
        delta, DINNER, DTRANK, b_dt, nullptr, nullptr);

    // 5) selective scan + fused gate -> yh/yl bf16
    scan_kernel<<<256, 256>>>(delta, u, dbc, A_log, Dvec, sres, yh, yl);

    // 6) out = y @ W_out
    mma_gemm3<1, 0><<<dim3(8, 32), 256, GEMM_SMEM>>>(
        yh, yl, DINNER, woutTh, woutTl, 0, DINNER,
        out, DMODEL, DINNER, nullptr, nullptr, nullptr);
}

// round 6
// speedup vs baseline: 1.2942x; 1.2942x over previous
#include <cuda_runtime.h>
#include <cuda_bf16.h>
#include <cstdint>

// Problem constants
#define BLROWS 4096   // B*L = 2*2048
#define LSEQ   2048
#define DMODEL 1024
#define DINNER 2048
#define DSTATE 16
#define DTRANK 64

typedef __nv_bfloat16 bf16;

// ---------------------------------------------------------------------------
// Scratch (device globals)
// ---------------------------------------------------------------------------
__device__ bf16  g_xsh[(size_t)BLROWS * DINNER];     // xs split (from GEMM1)
__device__ bf16  g_xsl[(size_t)BLROWS * DINNER];
__device__ float g_sres[(size_t)BLROWS * DINNER];    // silu(res)
__device__ float g_u  [(size_t)BLROWS * DINNER];     // silu(conv)
__device__ float g_dbc[(size_t)BLROWS * 96];
__device__ float g_delta[(size_t)BLROWS * DINNER];
__device__ float g_y [(size_t)BLROWS * DINNER];      // gated y (fp32)
// Transposed weights
__device__ float g_WinT [(size_t)4096 * 1024];                       // fp32
__device__ bf16  g_convTh[(size_t)4 * 2048 * 1024], g_convTl[(size_t)4 * 2048 * 1024];
__device__ float g_WoutT[(size_t)1024 * 2048];                       // fp32
__device__ float g_WdtT [(size_t)2048 * 64];                         // fp32

// ---------------------------------------------------------------------------
// PTX helpers
// ---------------------------------------------------------------------------
__device__ __forceinline__ uint32_t smem_u32(const void* p) {
    uint32_t a;
    asm("{ .reg .u64 t; cvta.to.shared.u64 t, %1; cvt.u32.u64 %0, t; }"
        : "=r"(a) : "l"(p));
    return a;
}
__device__ __forceinline__ void ldsm4(uint32_t* r, uint32_t addr) {
    asm volatile("ldmatrix.sync.aligned.m8n8.x4.shared.b16 {%0,%1,%2,%3}, [%4];"
        : "=r"(r[0]), "=r"(r[1]), "=r"(r[2]), "=r"(r[3]) : "r"(addr));
}
__device__ __forceinline__ void mma16816(
    float& d0, float& d1, float& d2, float& d3,
    uint32_t a0, uint32_t a1, uint32_t a2, uint32_t a3,
    uint32_t b0, uint32_t b1)
{
    asm volatile(
        "mma.sync.aligned.m16n8k16.row.col.f32.bf16.bf16.f32 "
        "{%0,%1,%2,%3}, {%4,%5,%6,%7}, {%8,%9}, {%0,%1,%2,%3};"
        : "+f"(d0), "+f"(d1), "+f"(d2), "+f"(d3)
        : "r"(a0), "r"(a1), "r"(a2), "r"(a3), "r"(b0), "r"(b1));
}
// bf16 2-way split of a pair of floats -> packed bf16x2 (hi, lo)
__device__ __forceinline__ void split2(float x, float y, uint32_t& hi, uint32_t& lo) {
    bf16 hx = __float2bfloat16_rn(x);
    bf16 hy = __float2bfloat16_rn(y);
    __nv_bfloat162 h; h.x = hx; h.y = hy;
    __nv_bfloat162 l = __floats2bfloat162_rn(x - __bfloat162float(hx),
                                             y - __bfloat162float(hy));
    hi = *reinterpret_cast<uint32_t*>(&h);
    lo = *reinterpret_cast<uint32_t*>(&l);
}
// SMEM tile row = 64B (32 bf16) in 4x16B chunks, xor-swizzled
__device__ __forceinline__ uint32_t swz(int row, int chunk) {
    return (uint32_t)((row << 6) + (((chunk ^ ((row >> 1) & 3)) & 3) << 4));
}
__device__ __forceinline__ float silu(float v) { return v / (1.f + __expf(-v)); }

// ---------------------------------------------------------------------------
// R3-proven bf16x3 mma GEMM (fp32 inputs, in-kernel split, single buffer,
// register prefetch, 2 syncs/iter).  C-tile[128,128] = A[M,K] @ Bt[N,K]^T.
// EPI: 0 fp32 store; 1 softplus+clip(+bias); 3 GEMM1 dual output
//      (n0<2048: xs->bf16 hi/lo;  n0>=2048: silu -> C fp32 at col-2048).
// ---------------------------------------------------------------------------
template <int EPI>
__global__ __launch_bounds__(256) void mma_gemm(
    const float* __restrict__ A, int lda,
    const float* __restrict__ Bt, int ldb,
    float* __restrict__ C, int ldc,
    int K, const float* __restrict__ bias,
    bf16* __restrict__ xsh, bf16* __restrict__ xsl)
{
    __shared__ __align__(16) char sAhi[8192], sAlo[8192], sBhi[8192], sBlo[8192];

    const int tid  = threadIdx.x;
    const int lane = tid & 31;
    const int wid  = tid >> 5;
    const int wm   = wid & 1;
    const int wn   = wid >> 1;
    const int m0   = blockIdx.y * 128;
    const int n0   = blockIdx.x * 128;
    const int TOT  = K >> 5;

    const uint32_t aHiB = smem_u32(sAhi), aLoB = smem_u32(sAlo);
    const uint32_t bHiB = smem_u32(sBhi), bLoB = smem_u32(sBlo);

    const int a_r  = lane & 15;
    const int a_cx = lane >> 4;
    const int b_r  = (lane & 7) + ((lane >> 4) << 3);
    const int b_cx = (lane >> 3) & 1;

    float acc[4][4][4];
#pragma unroll
    for (int i = 0; i < 4; i++)
#pragma unroll
        for (int j = 0; j < 4; j++)
#pragma unroll
            for (int k = 0; k < 4; k++) acc[i][j][k] = 0.f;

    float4 pa[4], pb[4];

    auto load = [&](int kb) {
#pragma unroll
        for (int i = 0; i < 4; i++) {
            int idx = tid + i * 256;
            int row = idx >> 3, seg = idx & 7;
            pa[i] = *(const float4*)(A + (size_t)(m0 + row) * lda + kb * 32 + seg * 4);
            pb[i] = *(const float4*)(Bt + (size_t)(n0 + row) * ldb + kb * 32 + seg * 4);
        }
    };

    auto store = [&]() {
#pragma unroll
        for (int i = 0; i < 4; i++) {
            int idx = tid + i * 256;
            int row = idx >> 3, seg = idx & 7;
            uint32_t off = swz(row, seg >> 1) + (seg & 1) * 8;
            uint2 h, l;
            split2(pa[i].x, pa[i].y, h.x, l.x);
            split2(pa[i].z, pa[i].w, h.y, l.y);
            *(uint2*)(sAhi + off) = h;
            *(uint2*)(sAlo + off) = l;
            split2(pb[i].x, pb[i].y, h.x, l.x);
            split2(pb[i].z, pb[i].w, h.y, l.y);
            *(uint2*)(sBhi + off) = h;
            *(uint2*)(sBlo + off) = l;
        }
    };

    auto mma_block = [&]() {
#pragma unroll
        for (int ks = 0; ks < 2; ks++) {
            uint32_t a[4][4], bh[4][2], bx[4][2];
#pragma unroll
            for (int mf = 0; mf < 4; mf++) {
                int row = wm * 64 + mf * 16 + a_r;
                ldsm4(a[mf], aHiB + swz(row, ks * 2 + a_cx));
            }
#pragma unroll
            for (int p = 0; p < 2; p++) {
                int row = wn * 32 + p * 16 + b_r;
                uint32_t t[4];
                ldsm4(t, bHiB + swz(row, ks * 2 + b_cx));
                bh[p * 2][0] = t[0]; bh[p * 2][1] = t[1];
                bh[p * 2 + 1][0] = t[2]; bh[p * 2 + 1][1] = t[3];
            }
#pragma unroll
            for (int mf = 0; mf < 4; mf++)
#pragma unroll
                for (int nf = 0; nf < 4; nf++)
                    mma16816(acc[mf][nf][0], acc[mf][nf][1], acc[mf][nf][2], acc[mf][nf][3],
                             a[mf][0], a[mf][1], a[mf][2], a[mf][3], bh[nf][0], bh[nf][1]);
#pragma unroll
            for (int p = 0; p < 2; p++) {
                int row = wn * 32 + p * 16 + b_r;
                uint32_t t[4];
                ldsm4(t, bLoB + swz(row, ks * 2 + b_cx));
                bx[p * 2][0] = t[0]; bx[p * 2][1] = t[1];
                bx[p * 2 + 1][0] = t[2]; bx[p * 2 + 1][1] = t[3];
            }
#pragma unroll
            for (int mf = 0; mf < 4; mf++)
#pragma unroll
                for (int nf = 0; nf < 4; nf++)
                    mma16816(acc[mf][nf][0], acc[mf][nf][1], acc[mf][nf][2], acc[mf][nf][3],
                             a[mf][0], a[mf][1], a[mf][2], a[mf][3], bx[nf][0], bx[nf][1]);
#pragma unroll
            for (int mf = 0; mf < 4; mf++) {
                int row = wm * 64 + mf * 16 + a_r;
                ldsm4(a[mf], aLoB + swz(row, ks * 2 + a_cx));
            }
#pragma unroll
            for (int mf = 0; mf < 4; mf++)
#pragma unroll
                for (int nf = 0; nf < 4; nf++)
                    mma16816(acc[mf][nf][0], acc[mf][nf][1], acc[mf][nf][2], acc[mf][nf][3],
                             a[mf][0], a[mf][1], a[mf][2], a[mf][3], bh[nf][0], bh[nf][1]);
        }
    };

    load(0);
    store();
    __syncthreads();
    for (int it = 1; it < TOT; it++) {
        load(it);
        mma_block();
        __syncthreads();
        store();
        __syncthreads();
    }
    mma_block();

    // Epilogue
#pragma unroll
    for (int mf = 0; mf < 4; mf++) {
        int r = m0 + wm * 64 + mf * 16 + (lane >> 2);
#pragma unroll
        for (int nf = 0; nf < 4; nf++) {
            int c = n0 + wn * 32 + nf * 8 + (lane & 3) * 2;
            float v0 = acc[mf][nf][0], v1 = acc[mf][nf][1];
            float v2 = acc[mf][nf][2], v3 = acc[mf][nf][3];
            if (EPI == 1) {
                float b0 = bias[c], b1 = bias[c + 1];
                float x0 = v0 + b0, x1 = v1 + b1, x2 = v2 + b0, x3 = v3 + b1;
                v0 = fminf(fmaxf(fmaxf(x0, 0.f) + log1pf(__expf(-fabsf(x0))), 1e-3f), 0.1f);
                v1 = fminf(fmaxf(fmaxf(x1, 0.f) + log1pf(__expf(-fabsf(x1))), 1e-3f), 0.1f);
                v2 = fminf(fmaxf(fmaxf(x2, 0.f) + log1pf(__expf(-fabsf(x2))), 1e-3f), 0.1f);
                v3 = fminf(fmaxf(fmaxf(x3, 0.f) + log1pf(__expf(-fabsf(x3))), 1e-3f), 0.1f);
            }
            if (EPI == 3) {
                if (n0 < 2048) {     // xs half -> bf16 hi/lo
                    uint32_t h, l;
                    split2(v0, v1, h, l);
                    *(uint32_t*)(xsh + (size_t)r * 2048 + c) = h;
                    *(uint32_t*)(xsl + (size_t)r * 2048 + c) = l;
                    split2(v2, v3, h, l);
                    *(uint32_t*)(xsh + (size_t)(r + 8) * 2048 + c) = h;
                    *(uint32_t*)(xsl + (size_t)(r + 8) * 2048 + c) = l;
                } else {             // res half -> silu -> sres fp32
                    int cc = c - 2048;
                    *(float2*)(C + (size_t)r * ldc + cc)
                        = make_float2(silu(v0), silu(v1));
                    *(float2*)(C + (size_t)(r + 8) * ldc + cc)
                        = make_float2(silu(v2), silu(v3));
                }
            } else {
                *(float2*)(C + (size_t)r * ldc + c)       = make_float2(v0, v1);
                *(float2*)(C + (size_t)(r + 8) * ldc + c) = make_float2(v2, v3);
            }
        }
    }
}

// ---------------------------------------------------------------------------
// Halo-fused grouped causal conv.  Per k-block: ONE 131-row A halo tile
// (pre-split bf16 xs) + all 4 taps' pre-split B tiles resident; 4 taps of
// mma against row-shifted ldmatrix views.  Double-buffered, 1 sync/k-block.
// Epilogue: +bias, silu -> U fp32.
// ---------------------------------------------------------------------------
#define CONV_STG  82944                      // 2*8704 (A hi/lo) + 4*16384 (B)
#define CONV_SMEM (2 * CONV_STG + 1024)

__global__ __launch_bounds__(256) void conv_halo(
    const bf16* __restrict__ Ah, const bf16* __restrict__ Al,   // xs [4096,2048]
    const bf16* __restrict__ Bh, const bf16* __restrict__ Bl,   // convT [4][2048,1024]
    const float* __restrict__ bias, float* __restrict__ U)
{
    extern __shared__ char dyn[];
    const uint32_t rawb = smem_u32(dyn);
    const uint32_t base = (rawb + 1023u) & ~1023u;
    char* tp = dyn + (base - rawb);

    const int tid  = threadIdx.x;
    const int lane = tid & 31;
    const int wid  = tid >> 5;
    const int wm   = wid & 1;
    const int wn   = wid >> 1;
    const int m0   = blockIdx.y * 128;
    const int n0   = blockIdx.x * 128;
    const int colbase = (n0 >= 1024) ? 1024 : 0;
    const bool headok = (m0 & (LSEQ - 1)) != 0;   // halo rows in same batch

    const int a_r  = lane & 15;
    const int a_cx = lane >> 4;
    const int b_r  = (lane & 7) + ((lane >> 4) << 3);
    const int b_cx = (lane >> 3) & 1;

    float acc[4][4][4];
#pragma unroll
    for (int i = 0; i < 4; i++)
#pragma unroll
        for (int j = 0; j < 4; j++)
#pragma unroll
            for (int k = 0; k < 4; k++) acc[i][j][k] = 0.f;

    uint4 sa[6], rb1[8], rb2[8];

    auto loadA = [&](int kb) {
#pragma unroll
        for (int i = 0; i < 3; i++) {
            int c = tid + i * 256;               // 524 chunks: 131 rows x 4 segs
            if (i < 2 || c < 524) {
                int row = c >> 2, seg = c & 3;
                bool valid = headok || (row >= 3);
                long grow = (long)m0 - 3 + row;
                if (valid) {
                    sa[i * 2]     = *(const uint4*)(Ah + grow * 2048 + colbase + kb * 32 + seg * 8);
                    sa[i * 2 + 1] = *(const uint4*)(Al + grow * 2048 + colbase + kb * 32 + seg * 8);
                } else {
                    sa[i * 2]     = make_uint4(0, 0, 0, 0);
                    sa[i * 2 + 1] = make_uint4(0, 0, 0, 0);
                }
            }
        }
    };
    auto stsA = [&](int s) {
        char* sb = tp + s * CONV_STG;
#pragma unroll
        for (int i = 0; i < 3; i++) {
            int c = tid + i * 256;
            if (i < 2 || c < 524) {
                int row = c >> 2, seg = c & 3;
                uint32_t off = swz(row, seg);
                *(uint4*)(sb + off)        = sa[i * 2];
                *(uint4*)(sb + 8704 + off) = sa[i * 2 + 1];
            }
        }
    };
    auto loadB = [&](int kb, int half, uint4* rb) {
#pragma unroll
        for (int i = 0; i < 4; i++) {
            int c = tid + i * 256;               // 1024 chunks = 2 taps x 512
            int tap = half * 2 + (c >> 9);
            int cc = c & 511;
            int row = cc >> 2, seg = cc & 3;
            const bf16* ph = Bh + (size_t)tap * 2048 * 1024 + (size_t)(n0 + row) * 1024 + kb * 32 + seg * 8;
            const bf16* pl = Bl + (size_t)tap * 2048 * 1024 + (size_t)(n0 + row) * 1024 + kb * 32 + seg * 8;
            rb[i * 2]     = *(const uint4*)ph;
            rb[i * 2 + 1] = *(const uint4*)pl;
        }
    };
    auto stsB = [&](int s, int half, uint4* rb) {
#pragma unroll
        for (int i = 0; i < 4; i++) {
            int c = tid + i * 256;
            int tap = half * 2 + (c >> 9);
            int cc = c & 511;
            int row = cc >> 2, seg = cc & 3;
            char* bb = tp + s * CONV_STG + 17408 + tap * 16384;
            uint32_t off = swz(row, seg);
            *(uint4*)(bb + off)        = rb[i * 2];
            *(uint4*)(bb + 8192 + off) = rb[i * 2 + 1];
        }
    };
    auto mma_tap = [&](int s, int tap) {
        uint32_t aHiB = base + (uint32_t)s * CONV_STG;
        uint32_t aLoB = aHiB + 8704;
        uint32_t bHiB = aHiB + 17408 + (uint32_t)tap * 16384;
        uint32_t bLoB = bHiB + 8192;
#pragma unroll
        for (int ks = 0; ks < 2; ks++) {
            uint32_t a[4][4], bh[4][2], bx[4][2];
#pragma unroll
            for (int mf = 0; mf < 4; mf++) {
                int row = wm * 64 + mf * 16 + a_r + tap;   // halo shift
                ldsm4(a[mf], aHiB + swz(row, ks * 2 + a_cx));
            }
#pragma unroll
            for (int p = 0; p < 2; p++) {
                int row = wn * 32 + p * 16 + b_r;
                uint32_t t[4];
                ldsm4(t, bHiB + swz(row, ks * 2 + b_cx));
                bh[p * 2][0] = t[0]; bh[p * 2][1] = t[1];
                bh[p * 2 + 1][0] = t[2]; bh[p * 2 + 1][1] = t[3];
            }
#pragma unroll
            for (int mf = 0; mf < 4; mf++)
#pragma unroll
                for (int nf = 0; nf < 4; nf++)
                    mma16816(acc[mf][nf][0], acc[mf][nf][1], acc[mf][nf][2], acc[mf][nf][3],
                             a[mf][0], a[mf][1], a[mf][2], a[mf][3], bh[nf][0], bh[nf][1]);
#pragma unroll
            for (int p = 0; p < 2; p++) {
                int row = wn * 32 + p * 16 + b_r;
                uint32_t t[4];
                ldsm4(t, bLoB + swz(row, ks * 2 + b_cx));
                bx[p * 2][0] = t[0]; bx[p * 2][1] = t[1];
                bx[p * 2 + 1][0] = t[2]; bx[p * 2 + 1][1] = t[3];
            }
#pragma unroll
            for (int mf = 0; mf < 4; mf++)
#pragma unroll
                for (int nf = 0; nf < 4; nf++)
                    mma16816(acc[mf][nf][0], acc[mf][nf][1], acc[mf][nf][2], acc[mf][nf][3],
                             a[mf][0], a[mf][1], a[mf][2], a[mf][3], bx[nf][0], bx[nf][1]);
#pragma unroll
            for (int mf = 0; mf < 4; mf++) {
                int row = wm * 64 + mf * 16 + a_r + tap;
                ldsm4(a[mf], aLoB + swz(row, ks * 2 + a_cx));
            }
#pragma unroll
            for (int mf = 0; mf < 4; mf++)
#pragma unroll
                for (int nf = 0; nf < 4; nf++)
                    mma16816(acc[mf][nf][0], acc[mf][nf][1], acc[mf][nf][2], acc[mf][nf][3],
                             a[mf][0], a[mf][1], a[mf][2], a[mf][3], bh[nf][0], bh[nf][1]);
        }
    };

    // Prologue
    loadA(0); loadB(0, 0, rb1); loadB(0, 1, rb2);
    stsA(0); stsB(0, 0, rb1); stsB(0, 1, rb2);
    __syncthreads();

    for (int kb = 0; kb < 32; kb++) {
        int cur = kb & 1, nxt = cur ^ 1;
        bool more = (kb + 1) < 32;
        if (more) { loadA(kb + 1); loadB(kb + 1, 0, rb1); }
        mma_tap(cur, 0);
        mma_tap(cur, 1);
        if (more) { stsA(nxt); stsB(nxt, 0, rb1); loadB(kb + 1, 1, rb2); }
        mma_tap(cur, 2);
        mma_tap(cur, 3);
        if (more) stsB(nxt, 1, rb2);
        __syncthreads();
    }

    // Epilogue: +bias, silu -> U
#pragma unroll
    for (int mf = 0; mf < 4; mf++) {
        int r = m0 + wm * 64 + mf * 16 + (lane >> 2);
#pragma unroll
        for (int nf = 0; nf < 4; nf++) {
            int c = n0 + wn * 32 + nf * 8 + (lane & 3) * 2;
            float b0 = bias[c], b1 = bias[c + 1];
            float v0 = silu(acc[mf][nf][0] + b0);
            float v1 = silu(acc[mf][nf][1] + b1);
            float v2 = silu(acc[mf][nf][2] + b0);
            float v3 = silu(acc[mf][nf][3] + b1);
            *(float2*)(U + (size_t)r * DINNER + c)       = make_float2(v0, v1);
            *(float2*)(U + (size_t)(r + 8) * DINNER + c) = make_float2(v2, v3);
        }
    }
}

// ---------------------------------------------------------------------------
// Fused weight preprocessing (one launch): z=0 Win->fp32T, z=1..4 conv tap
// ->bf16-split T, z=5 Wout->fp32T, z=6 Wdt->fp32T.
// ---------------------------------------------------------------------------
__global__ __launch_bounds__(256) void fused_transpose(
    const float* __restrict__ Win, const float* __restrict__ convk,
    const float* __restrict__ Wout, const float* __restrict__ Wdt,
    float* __restrict__ winT, bf16* __restrict__ cTh, bf16* __restrict__ cTl,
    float* __restrict__ woutT, float* __restrict__ wdtT)
{
    int z = blockIdx.z;
    const float* src; int R, C;
    if (z == 0)      { src = Win;  R = 1024; C = 4096; }
    else if (z <= 4) { src = convk + (size_t)(z - 1) * 1024 * 2048; R = 1024; C = 2048; }
    else if (z == 5) { src = Wout; R = 2048; C = 1024; }
    else             { src = Wdt;  R = 64;   C = 2048; }
    if (blockIdx.x * 32 >= C || blockIdx.y * 32 >= R) return;

    __shared__ float t[32][33];
    int x = blockIdx.x * 32 + threadIdx.x;
#pragma unroll
    for (int j = 0; j < 4; j++) {
        int y = blockIdx.y * 32 + threadIdx.y + j * 8;
        t[threadIdx.y + j * 8][threadIdx.x] = src[(size_t)y * C + x];
    }
    __syncthreads();
    int x2 = blockIdx.y * 32 + threadIdx.x;
#pragma unroll
    for (int j = 0; j < 4; j++) {
        int y2 = blockIdx.x * 32 + threadIdx.y + j * 8;
        float v = t[threadIdx.x][threadIdx.y + j * 8];
        if (z == 0) {
            winT[(size_t)y2 * R + x2] = v;
        } else if (z <= 4) {
            size_t off = (size_t)(z - 1) * 2048 * 1024 + (size_t)y2 * R + x2;
            bf16 h = __float2bfloat16_rn(v);
            cTh[off] = h;
            cTl[off] = __float2bfloat16_rn(v - __bfloat162float(h));
        } else if (z == 5) {
            woutT[(size_t)y2 * R + x2] = v;
        } else {
            wdtT[(size_t)y2 * R + x2] = v;
        }
    }
}

// ---------------------------------------------------------------------------
// Narrow GEMM: DBC[4096,96] = U @ W_x (fp32 SIMT)
// ---------------------------------------------------------------------------
__global__ __launch_bounds__(256) void gemm_n96_kernel(
    const float* __restrict__ A, const float* __restrict__ B, float* __restrict__ C)
{
    const int BK = 32, NN = 96;
    __shared__ float As[BK][32];
    __shared__ float Bs[BK][NN];

    const int m0 = blockIdx.x * 32;
    const int tid = threadIdx.x;
    const int tx = tid & 15;
    const int ty = tid >> 4;

    float acc[2][6];
#pragma unroll
    for (int r = 0; r < 2; r++)
#pragma unroll
        for (int j = 0; j < 6; j++) acc[r][j] = 0.f;

    for (int k0 = 0; k0 < DINNER; k0 += BK) {
        {
            int row = tid >> 3;
            int cv  = (tid & 7) * 4;
            float4 a = *(const float4*)(A + (size_t)(m0 + row) * DINNER + k0 + cv);
            As[cv + 0][row] = a.x; As[cv + 1][row] = a.y;
            As[cv + 2][row] = a.z; As[cv + 3][row] = a.w;
        }
#pragma unroll
        for (int i = 0; i < 3; i++) {
            int idx  = tid + i * 256;
            int rowB = idx / 24;
            int cv   = (idx % 24) * 4;
            *(float4*)(&Bs[rowB][cv]) =
                *(const float4*)(B + (size_t)(k0 + rowB) * NN + cv);
        }
        __syncthreads();
#pragma unroll
        for (int k = 0; k < BK; k++) {
            float a0 = As[k][ty * 2];
            float a1 = As[k][ty * 2 + 1];
#pragma unroll
            for (int j = 0; j < 6; j++) {
                float bb = Bs[k][tx * 6 + j];
                acc[0][j] = fmaf(a0, bb, acc[0][j]);
                acc[1][j] = fmaf(a1, bb, acc[1][j]);
            }
        }
        __syncthreads();
    }
#pragma unroll
    for (int r = 0; r < 2; r++) {
        int m = m0 + ty * 2 + r;
#pragma unroll
        for (int j = 0; j < 6; j++)
            C[(size_t)m * 96 + tx * 6 + j] = acc[r][j];
    }
}

// ---------------------------------------------------------------------------
// Selective scan with fused gate: y = (scan + u*D) * silu(res)  (fp32)
// ---------------------------------------------------------------------------
__global__ __launch_bounds__(256) void scan_kernel(
    const float* __restrict__ delta, const float* __restrict__ u,
    const float* __restrict__ dbc, const float* __restrict__ A_log,
    const float* __restrict__ Dp, const float* __restrict__ sres,
    float* __restrict__ Y)
{
    int tid = blockIdx.x * blockDim.x + threadIdx.x;
    int n = tid & 15;
    int d = (tid >> 4) & (DINNER - 1);
    int b = tid >> 15;

    const float a  = -__expf(A_log[d * DSTATE + n]);
    const float Dd = Dp[d];

    const size_t rowbase = (size_t)b * LSEQ;
    const float* dptr = delta + rowbase * DINNER + d;
    const float* uptr = u     + rowbase * DINNER + d;
    const float* bc   = dbc   + rowbase * 96;
    const float* rp   = sres  + rowbase * DINNER + d;
    float*       yp   = Y     + rowbase * DINNER + d;

    float h = 0.f;
    for (int t = 0; t < LSEQ; t++) {
        float de = dptr[(size_t)t * DINNER];
        float uu = uptr[(size_t)t * DINNER];
        float Bn = bc[t * 96 + DTRANK + n];
        float Cn = bc[t * 96 + DTRANK + DSTATE + n];
        float dA = __expf(de * a);
        h = fmaf(dA, h, de * uu * Bn);
        float p = h * Cn;
        p += __shfl_xor_sync(0xffffffffu, p, 8);
        p += __shfl_xor_sync(0xffffffffu, p, 4);
        p += __shfl_xor_sync(0xffffffffu, p, 2);
        p += __shfl_xor_sync(0xffffffffu, p, 1);
        if (n == 0)
            yp[(size_t)t * DINNER] = fmaf(uu, Dd, p) * rp[(size_t)t * DINNER];
    }
}

// ---------------------------------------------------------------------------
// Launch
// ---------------------------------------------------------------------------
extern "C" void kernel_launch(void* const* d_in, const int* in_sizes, int n_in,
                              void* d_out, int out_size)
{
    (void)in_sizes; (void)n_in; (void)out_size;
    const float* x      = (const float*)d_in[0];
    const float* W_in   = (const float*)d_in[1];
    const float* conv_k = (const float*)d_in[2];
    const float* conv_b = (const float*)d_in[3];
    const float* W_x    = (const float*)d_in[4];
    const float* W_dt   = (const float*)d_in[5];
    const float* b_dt   = (const float*)d_in[6];
    const float* A_log  = (const float*)d_in[7];
    const float* Dvec   = (const float*)d_in[8];
    const float* W_out  = (const float*)d_in[9];
    float* out = (float*)d_out;

    bf16 *xsh, *xsl, *convTh, *convTl;
    float *sres, *u, *dbc, *delta, *y, *winT, *woutT, *wdtT;
    cudaGetSymbolAddress((void**)&xsh,   g_xsh);
    cudaGetSymbolAddress((void**)&xsl,   g_xsl);
    cudaGetSymbolAddress((void**)&sres,  g_sres);
    cudaGetSymbolAddress((void**)&u,     g_u);
    cudaGetSymbolAddress((void**)&dbc,   g_dbc);
    cudaGetSymbolAddress((void**)&delta, g_delta);
    cudaGetSymbolAddress((void**)&y,     g_y);
    cudaGetSymbolAddress((void**)&winT,  g_WinT);
    cudaGetSymbolAddress((void**)&convTh, g_convTh);
    cudaGetSymbolAddress((void**)&convTl, g_convTl);
    cudaGetSymbolAddress((void**)&woutT, g_WoutT);
    cudaGetSymbolAddress((void**)&wdtT,  g_WdtT);

    cudaFuncSetAttribute(conv_halo, cudaFuncAttributeMaxDynamicSharedMemorySize, CONV_SMEM);

    // 0) all weight preprocessing in ONE launch
    fused_transpose<<<dim3(128, 64, 7), dim3(32, 8)>>>(
        W_in, conv_k, W_out, W_dt, winT, convTh, convTl, woutT, wdtT);

    // 1) GEMM1: xs -> bf16 hi/lo,  silu(res) -> sres fp32
    mma_gemm<3><<<dim3(32, 32), 256>>>(
        x, DMODEL, winT, DMODEL, sres, DINNER, DMODEL, nullptr, xsh, xsl);

    // 2) halo-fused grouped causal conv + bias + silu -> u fp32
    conv_halo<<<dim3(16, 32), 256, CONV_SMEM>>>(
        xsh, xsl, convTh, convTl, conv_b, u);

    // 3) dbc = u @ W_x
    gemm_n96_kernel<<<128, 256>>>(u, W_x, dbc);

    // 4) delta = clip(softplus(dt_raw @ W_dt + b_dt))
    mma_gemm<1><<<dim3(16, 32), 256>>>(
        dbc, 96, wdtT, DTRANK, delta, DINNER, DTRANK, b_dt, nullptr, nullptr);

    // 5) selective scan + fused gate -> y fp32   (profiled launch #5)
    scan_kernel<<<256, 256>>>(delta, u, dbc, A_log, Dvec, sres, y);

    // 6) out = y @ W_out
    mma_gemm<0><<<dim3(8, 32), 256>>>(
        y, DINNER, woutT, DINNER, out, DMODEL, DINNER, nullptr, nullptr, nullptr);
}

// round 7
// speedup vs baseline: 1.3224x; 1.0218x over previous
#include <cuda_runtime.h>
#include <cuda_bf16.h>
#include <cstdint>

// Problem constants
#define BLROWS 4096   // B*L = 2*2048
#define LSEQ   2048
#define DMODEL 1024
#define DINNER 2048
#define DSTATE 16
#define DTRANK 64

typedef __nv_bfloat16 bf16;

// ---------------------------------------------------------------------------
// Scratch (device globals)
// ---------------------------------------------------------------------------
__device__ bf16  g_xsh[(size_t)BLROWS * DINNER];     // xs split (from GEMM1)
__device__ bf16  g_xsl[(size_t)BLROWS * DINNER];
__device__ float g_sres[(size_t)BLROWS * DINNER];    // silu(res)
__device__ float g_u  [(size_t)BLROWS * DINNER];     // silu(conv)
__device__ float g_dbc[(size_t)BLROWS * 96];
__device__ float g_dbc_part[(size_t)8 * BLROWS * 96];   // split-K partials
__device__ float g_delta[(size_t)BLROWS * DINNER];
__device__ float g_y [(size_t)BLROWS * DINNER];      // gated y (fp32)
// Transposed weights
__device__ float g_WinT [(size_t)4096 * 1024];                       // fp32
__device__ bf16  g_convTh[(size_t)4 * 2048 * 1024], g_convTl[(size_t)4 * 2048 * 1024];
__device__ float g_WoutT[(size_t)1024 * 2048];                       // fp32
__device__ float g_WdtT [(size_t)2048 * 64];                         // fp32

// ---------------------------------------------------------------------------
// PTX helpers
// ---------------------------------------------------------------------------
__device__ __forceinline__ uint32_t smem_u32(const void* p) {
    uint32_t a;
    asm("{ .reg .u64 t; cvta.to.shared.u64 t, %1; cvt.u32.u64 %0, t; }"
        : "=r"(a) : "l"(p));
    return a;
}
__device__ __forceinline__ void ldsm4(uint32_t* r, uint32_t addr) {
    asm volatile("ldmatrix.sync.aligned.m8n8.x4.shared.b16 {%0,%1,%2,%3}, [%4];"
        : "=r"(r[0]), "=r"(r[1]), "=r"(r[2]), "=r"(r[3]) : "r"(addr));
}
__device__ __forceinline__ void mma16816(
    float& d0, float& d1, float& d2, float& d3,
    uint32_t a0, uint32_t a1, uint32_t a2, uint32_t a3,
    uint32_t b0, uint32_t b1)
{
    asm volatile(
        "mma.sync.aligned.m16n8k16.row.col.f32.bf16.bf16.f32 "
        "{%0,%1,%2,%3}, {%4,%5,%6,%7}, {%8,%9}, {%0,%1,%2,%3};"
        : "+f"(d0), "+f"(d1), "+f"(d2), "+f"(d3)
        : "r"(a0), "r"(a1), "r"(a2), "r"(a3), "r"(b0), "r"(b1));
}
// bf16 2-way split of a pair of floats -> packed bf16x2 (hi, lo)
__device__ __forceinline__ void split2(float x, float y, uint32_t& hi, uint32_t& lo) {
    bf16 hx = __float2bfloat16_rn(x);
    bf16 hy = __float2bfloat16_rn(y);
    __nv_bfloat162 h; h.x = hx; h.y = hy;
    __nv_bfloat162 l = __floats2bfloat162_rn(x - __bfloat162float(hx),
                                             y - __bfloat162float(hy));
    hi = *reinterpret_cast<uint32_t*>(&h);
    lo = *reinterpret_cast<uint32_t*>(&l);
}
// SMEM tile row = 64B (32 bf16) in 4x16B chunks, xor-swizzled
__device__ __forceinline__ uint32_t swz(int row, int chunk) {
    return (uint32_t)((row << 6) + (((chunk ^ ((row >> 1) & 3)) & 3) << 4));
}
__device__ __forceinline__ float silu(float v) { return v / (1.f + __expf(-v)); }

// ---------------------------------------------------------------------------
// R3-proven bf16x3 mma GEMM (fp32 inputs, in-kernel split, single buffer,
// register prefetch, 2 syncs/iter).  C-tile[128,128] = A[M,K] @ Bt[N,K]^T.
// EPI: 0 fp32 store; 1 softplus+clip(+bias); 3 GEMM1 dual output.
// ---------------------------------------------------------------------------
template <int EPI>
__global__ __launch_bounds__(256) void mma_gemm(
    const float* __restrict__ A, int lda,
    const float* __restrict__ Bt, int ldb,
    float* __restrict__ C, int ldc,
    int K, const float* __restrict__ bias,
    bf16* __restrict__ xsh, bf16* __restrict__ xsl)
{
    __shared__ __align__(16) char sAhi[8192], sAlo[8192], sBhi[8192], sBlo[8192];

    const int tid  = threadIdx.x;
    const int lane = tid & 31;
    const int wid  = tid >> 5;
    const int wm   = wid & 1;
    const int wn   = wid >> 1;
    const int m0   = blockIdx.y * 128;
    const int n0   = blockIdx.x * 128;
    const int TOT  = K >> 5;

    const uint32_t aHiB = smem_u32(sAhi), aLoB = smem_u32(sAlo);
    const uint32_t bHiB = smem_u32(sBhi), bLoB = smem_u32(sBlo);

    const int a_r  = lane & 15;
    const int a_cx = lane >> 4;
    const int b_r  = (lane & 7) + ((lane >> 4) << 3);
    const int b_cx = (lane >> 3) & 1;

    float acc[4][4][4];
#pragma unroll
    for (int i = 0; i < 4; i++)
#pragma unroll
        for (int j = 0; j < 4; j++)
#pragma unroll
            for (int k = 0; k < 4; k++) acc[i][j][k] = 0.f;

    float4 pa[4], pb[4];

    auto load = [&](int kb) {
#pragma unroll
        for (int i = 0; i < 4; i++) {
            int idx = tid + i * 256;
            int row = idx >> 3, seg = idx & 7;
            pa[i] = *(const float4*)(A + (size_t)(m0 + row) * lda + kb * 32 + seg * 4);
            pb[i] = *(const float4*)(Bt + (size_t)(n0 + row) * ldb + kb * 32 + seg * 4);
        }
    };

    auto store = [&]() {
#pragma unroll
        for (int i = 0; i < 4; i++) {
            int idx = tid + i * 256;
            int row = idx >> 3, seg = idx & 7;
            uint32_t off = swz(row, seg >> 1) + (seg & 1) * 8;
            uint2 h, l;
            split2(pa[i].x, pa[i].y, h.x, l.x);
            split2(pa[i].z, pa[i].w, h.y, l.y);
            *(uint2*)(sAhi + off) = h;
            *(uint2*)(sAlo + off) = l;
            split2(pb[i].x, pb[i].y, h.x, l.x);
            split2(pb[i].z, pb[i].w, h.y, l.y);
            *(uint2*)(sBhi + off) = h;
            *(uint2*)(sBlo + off) = l;
        }
    };

    auto mma_block = [&]() {
#pragma unroll
        for (int ks = 0; ks < 2; ks++) {
            uint32_t a[4][4], bh[4][2], bx[4][2];
#pragma unroll
            for (int mf = 0; mf < 4; mf++) {
                int row = wm * 64 + mf * 16 + a_r;
                ldsm4(a[mf], aHiB + swz(row, ks * 2 + a_cx));
            }
#pragma unroll
            for (int p = 0; p < 2; p++) {
                int row = wn * 32 + p * 16 + b_r;
                uint32_t t[4];
                ldsm4(t, bHiB + swz(row, ks * 2 + b_cx));
                bh[p * 2][0] = t[0]; bh[p * 2][1] = t[1];
                bh[p * 2 + 1][0] = t[2]; bh[p * 2 + 1][1] = t[3];
            }
#pragma unroll
            for (int mf = 0; mf < 4; mf++)
#pragma unroll
                for (int nf = 0; nf < 4; nf++)
                    mma16816(acc[mf][nf][0], acc[mf][nf][1], acc[mf][nf][2], acc[mf][nf][3],
                             a[mf][0], a[mf][1], a[mf][2], a[mf][3], bh[nf][0], bh[nf][1]);
#pragma unroll
            for (int p = 0; p < 2; p++) {
                int row = wn * 32 + p * 16 + b_r;
                uint32_t t[4];
                ldsm4(t, bLoB + swz(row, ks * 2 + b_cx));
                bx[p * 2][0] = t[0]; bx[p * 2][1] = t[1];
                bx[p * 2 + 1][0] = t[2]; bx[p * 2 + 1][1] = t[3];
            }
#pragma unroll
            for (int mf = 0; mf < 4; mf++)
#pragma unroll
                for (int nf = 0; nf < 4; nf++)
                    mma16816(acc[mf][nf][0], acc[mf][nf][1], acc[mf][nf][2], acc[mf][nf][3],
                             a[mf][0], a[mf][1], a[mf][2], a[mf][3], bx[nf][0], bx[nf][1]);
#pragma unroll
            for (int mf = 0; mf < 4; mf++) {
                int row = wm * 64 + mf * 16 + a_r;
                ldsm4(a[mf], aLoB + swz(row, ks * 2 + a_cx));
            }
#pragma unroll
            for (int mf = 0; mf < 4; mf++)
#pragma unroll
                for (int nf = 0; nf < 4; nf++)
                    mma16816(acc[mf][nf][0], acc[mf][nf][1], acc[mf][nf][2], acc[mf][nf][3],
                             a[mf][0], a[mf][1], a[mf][2], a[mf][3], bh[nf][0], bh[nf][1]);
        }
    };

    load(0);
    store();
    __syncthreads();
    for (int it = 1; it < TOT; it++) {
        load(it);
        mma_block();
        __syncthreads();
        store();
        __syncthreads();
    }
    mma_block();

    // Epilogue
#pragma unroll
    for (int mf = 0; mf < 4; mf++) {
        int r = m0 + wm * 64 + mf * 16 + (lane >> 2);
#pragma unroll
        for (int nf = 0; nf < 4; nf++) {
            int c = n0 + wn * 32 + nf * 8 + (lane & 3) * 2;
            float v0 = acc[mf][nf][0], v1 = acc[mf][nf][1];
            float v2 = acc[mf][nf][2], v3 = acc[mf][nf][3];
            if (EPI == 1) {
                float b0 = bias[c], b1 = bias[c + 1];
                float x0 = v0 + b0, x1 = v1 + b1, x2 = v2 + b0, x3 = v3 + b1;
                v0 = fminf(fmaxf(fmaxf(x0, 0.f) + log1pf(__expf(-fabsf(x0))), 1e-3f), 0.1f);
                v1 = fminf(fmaxf(fmaxf(x1, 0.f) + log1pf(__expf(-fabsf(x1))), 1e-3f), 0.1f);
                v2 = fminf(fmaxf(fmaxf(x2, 0.f) + log1pf(__expf(-fabsf(x2))), 1e-3f), 0.1f);
                v3 = fminf(fmaxf(fmaxf(x3, 0.f) + log1pf(__expf(-fabsf(x3))), 1e-3f), 0.1f);
            }
            if (EPI == 3) {
                if (n0 < 2048) {     // xs half -> bf16 hi/lo
                    uint32_t h, l;
                    split2(v0, v1, h, l);
                    *(uint32_t*)(xsh + (size_t)r * 2048 + c) = h;
                    *(uint32_t*)(xsl + (size_t)r * 2048 + c) = l;
                    split2(v2, v3, h, l);
                    *(uint32_t*)(xsh + (size_t)(r + 8) * 2048 + c) = h;
                    *(uint32_t*)(xsl + (size_t)(r + 8) * 2048 + c) = l;
                } else {             // res half -> silu -> sres fp32
                    int cc = c - 2048;
                    *(float2*)(C + (size_t)r * ldc + cc)
                        = make_float2(silu(v0), silu(v1));
                    *(float2*)(C + (size_t)(r + 8) * ldc + cc)
                        = make_float2(silu(v2), silu(v3));
                }
            } else {
                *(float2*)(C + (size_t)r * ldc + c)       = make_float2(v0, v1);
                *(float2*)(C + (size_t)(r + 8) * ldc + c) = make_float2(v2, v3);
            }
        }
    }
}

// ---------------------------------------------------------------------------
// Halo-fused grouped causal conv (R6-proven).
// ---------------------------------------------------------------------------
#define CONV_STG  82944                      // 2*8704 (A hi/lo) + 4*16384 (B)
#define CONV_SMEM (2 * CONV_STG + 1024)

__global__ __launch_bounds__(256) void conv_halo(
    const bf16* __restrict__ Ah, const bf16* __restrict__ Al,   // xs [4096,2048]
    const bf16* __restrict__ Bh, const bf16* __restrict__ Bl,   // convT [4][2048,1024]
    const float* __restrict__ bias, float* __restrict__ U)
{
    extern __shared__ char dyn[];
    const uint32_t rawb = smem_u32(dyn);
    const uint32_t base = (rawb + 1023u) & ~1023u;
    char* tp = dyn + (base - rawb);

    const int tid  = threadIdx.x;
    const int lane = tid & 31;
    const int wid  = tid >> 5;
    const int wm   = wid & 1;
    const int wn   = wid >> 1;
    const int m0   = blockIdx.y * 128;
    const int n0   = blockIdx.x * 128;
    const int colbase = (n0 >= 1024) ? 1024 : 0;
    const bool headok = (m0 & (LSEQ - 1)) != 0;

    const int a_r  = lane & 15;
    const int a_cx = lane >> 4;
    const int b_r  = (lane & 7) + ((lane >> 4) << 3);
    const int b_cx = (lane >> 3) & 1;

    float acc[4][4][4];
#pragma unroll
    for (int i = 0; i < 4; i++)
#pragma unroll
        for (int j = 0; j < 4; j++)
#pragma unroll
            for (int k = 0; k < 4; k++) acc[i][j][k] = 0.f;

    uint4 sa[6], rb1[8], rb2[8];

    auto loadA = [&](int kb) {
#pragma unroll
        for (int i = 0; i < 3; i++) {
            int c = tid + i * 256;
            if (i < 2 || c < 524) {
                int row = c >> 2, seg = c & 3;
                bool valid = headok || (row >= 3);
                long grow = (long)m0 - 3 + row;
                if (valid) {
                    sa[i * 2]     = *(const uint4*)(Ah + grow * 2048 + colbase + kb * 32 + seg * 8);
                    sa[i * 2 + 1] = *(const uint4*)(Al + grow * 2048 + colbase + kb * 32 + seg * 8);
                } else {
                    sa[i * 2]     = make_uint4(0, 0, 0, 0);
                    sa[i * 2 + 1] = make_uint4(0, 0, 0, 0);
                }
            }
        }
    };
    auto stsA = [&](int s) {
        char* sb = tp + s * CONV_STG;
#pragma unroll
        for (int i = 0; i < 3; i++) {
            int c = tid + i * 256;
            if (i < 2 || c < 524) {
                int row = c >> 2, seg = c & 3;
                uint32_t off = swz(row, seg);
                *(uint4*)(sb + off)        = sa[i * 2];
                *(uint4*)(sb + 8704 + off) = sa[i * 2 + 1];
            }
        }
    };
    auto loadB = [&](int kb, int half, uint4* rb) {
#pragma unroll
        for (int i = 0; i < 4; i++) {
            int c = tid + i * 256;
            int tap = half * 2 + (c >> 9);
            int cc = c & 511;
            int row = cc >> 2, seg = cc & 3;
            const bf16* ph = Bh + (size_t)tap * 2048 * 1024 + (size_t)(n0 + row) * 1024 + kb * 32 + seg * 8;
            const bf16* pl = Bl + (size_t)tap * 2048 * 1024 + (size_t)(n0 + row) * 1024 + kb * 32 + seg * 8;
            rb[i * 2]     = *(const uint4*)ph;
            rb[i * 2 + 1] = *(const uint4*)pl;
        }
    };
    auto stsB = [&](int s, int half, uint4* rb) {
#pragma unroll
        for (int i = 0; i < 4; i++) {
            int c = tid + i * 256;
            int tap = half * 2 + (c >> 9);
            int cc = c & 511;
            int row = cc >> 2, seg = cc & 3;
            char* bb = tp + s * CONV_STG + 17408 + tap * 16384;
            uint32_t off = swz(row, seg);
            *(uint4*)(bb + off)        = rb[i * 2];
            *(uint4*)(bb + 8192 + off) = rb[i * 2 + 1];
        }
    };
    auto mma_tap = [&](int s, int tap) {
        uint32_t aHiB = base + (uint32_t)s * CONV_STG;
        uint32_t aLoB = aHiB + 8704;
        uint32_t bHiB = aHiB + 17408 + (uint32_t)tap * 16384;
        uint32_t bLoB = bHiB + 8192;
#pragma unroll
        for (int ks = 0; ks < 2; ks++) {
            uint32_t a[4][4], bh[4][2], bx[4][2];
#pragma unroll
            for (int mf = 0; mf < 4; mf++) {
                int row = wm * 64 + mf * 16 + a_r + tap;
                ldsm4(a[mf], aHiB + swz(row, ks * 2 + a_cx));
            }
#pragma unroll
            for (int p = 0; p < 2; p++) {
                int row = wn * 32 + p * 16 + b_r;
                uint32_t t[4];
                ldsm4(t, bHiB + swz(row, ks * 2 + b_cx));
                bh[p * 2][0] = t[0]; bh[p * 2][1] = t[1];
                bh[p * 2 + 1][0] = t[2]; bh[p * 2 + 1][1] = t[3];
            }
#pragma unroll
            for (int mf = 0; mf < 4; mf++)
#pragma unroll
                for (int nf = 0; nf < 4; nf++)
                    mma16816(acc[mf][nf][0], acc[mf][nf][1], acc[mf][nf][2], acc[mf][nf][3],
                             a[mf][0], a[mf][1], a[mf][2], a[mf][3], bh[nf][0], bh[nf][1]);
#pragma unroll
            for (int p = 0; p < 2; p++) {
                int row = wn * 32 + p * 16 + b_r;
                uint32_t t[4];
                ldsm4(t, bLoB + swz(row, ks * 2 + b_cx));
                bx[p * 2][0] = t[0]; bx[p * 2][1] = t[1];
                bx[p * 2 + 1][0] = t[2]; bx[p * 2 + 1][1] = t[3];
            }
#pragma unroll
            for (int mf = 0; mf < 4; mf++)
#pragma unroll
                for (int nf = 0; nf < 4; nf++)
                    mma16816(acc[mf][nf][0], acc[mf][nf][1], acc[mf][nf][2], acc[mf][nf][3],
                             a[mf][0], a[mf][1], a[mf][2], a[mf][3], bx[nf][0], bx[nf][1]);
#pragma unroll
            for (int mf = 0; mf < 4; mf++) {
                int row = wm * 64 + mf * 16 + a_r + tap;
                ldsm4(a[mf], aLoB + swz(row, ks * 2 + a_cx));
            }
#pragma unroll
            for (int mf = 0; mf < 4; mf++)
#pragma unroll
                for (int nf = 0; nf < 4; nf++)
                    mma16816(acc[mf][nf][0], acc[mf][nf][1], acc[mf][nf][2], acc[mf][nf][3],
                             a[mf][0], a[mf][1], a[mf][2], a[mf][3], bh[nf][0], bh[nf][1]);
        }
    };

    loadA(0); loadB(0, 0, rb1); loadB(0, 1, rb2);
    stsA(0); stsB(0, 0, rb1); stsB(0, 1, rb2);
    __syncthreads();

    for (int kb = 0; kb < 32; kb++) {
        int cur = kb & 1, nxt = cur ^ 1;
        bool more = (kb + 1) < 32;
        if (more) { loadA(kb + 1); loadB(kb + 1, 0, rb1); }
        mma_tap(cur, 0);
        mma_tap(cur, 1);
        if (more) { stsA(nxt); stsB(nxt, 0, rb1); loadB(kb + 1, 1, rb2); }
        mma_tap(cur, 2);
        mma_tap(cur, 3);
        if (more) stsB(nxt, 1, rb2);
        __syncthreads();
    }

#pragma unroll
    for (int mf = 0; mf < 4; mf++) {
        int r = m0 + wm * 64 + mf * 16 + (lane >> 2);
#pragma unroll
        for (int nf = 0; nf < 4; nf++) {
            int c = n0 + wn * 32 + nf * 8 + (lane & 3) * 2;
            float b0 = bias[c], b1 = bias[c + 1];
            float v0 = silu(acc[mf][nf][0] + b0);
            float v1 = silu(acc[mf][nf][1] + b1);
            float v2 = silu(acc[mf][nf][2] + b0);
            float v3 = silu(acc[mf][nf][3] + b1);
            *(float2*)(U + (size_t)r * DINNER + c)       = make_float2(v0, v1);
            *(float2*)(U + (size_t)(r + 8) * DINNER + c) = make_float2(v2, v3);
        }
    }
}

// ---------------------------------------------------------------------------
// Fused weight preprocessing (one launch)
// ---------------------------------------------------------------------------
__global__ __launch_bounds__(256) void fused_transpose(
    const float* __restrict__ Win, const float* __restrict__ convk,
    const float* __restrict__ Wout, const float* __restrict__ Wdt,
    float* __restrict__ winT, bf16* __restrict__ cTh, bf16* __restrict__ cTl,
    float* __restrict__ woutT, float* __restrict__ wdtT)
{
    int z = blockIdx.z;
    const float* src; int R, C;
    if (z == 0)      { src = Win;  R = 1024; C = 4096; }
    else if (z <= 4) { src = convk + (size_t)(z - 1) * 1024 * 2048; R = 1024; C = 2048; }
    else if (z == 5) { src = Wout; R = 2048; C = 1024; }
    else             { src = Wdt;  R = 64;   C = 2048; }
    if (blockIdx.x * 32 >= C || blockIdx.y * 32 >= R) return;

    __shared__ float t[32][33];
    int x = blockIdx.x * 32 + threadIdx.x;
#pragma unroll
    for (int j = 0; j < 4; j++) {
        int y = blockIdx.y * 32 + threadIdx.y + j * 8;
        t[threadIdx.y + j * 8][threadIdx.x] = src[(size_t)y * C + x];
    }
    __syncthreads();
    int x2 = blockIdx.y * 32 + threadIdx.x;
#pragma unroll
    for (int j = 0; j < 4; j++) {
        int y2 = blockIdx.x * 32 + threadIdx.y + j * 8;
        float v = t[threadIdx.x][threadIdx.y + j * 8];
        if (z == 0) {
            winT[(size_t)y2 * R + x2] = v;
        } else if (z <= 4) {
            size_t off = (size_t)(z - 1) * 2048 * 1024 + (size_t)y2 * R + x2;
            bf16 h = __float2bfloat16_rn(v);
            cTh[off] = h;
            cTl[off] = __float2bfloat16_rn(v - __bfloat162float(h));
        } else if (z == 5) {
            woutT[(size_t)y2 * R + x2] = v;
        } else {
            wdtT[(size_t)y2 * R + x2] = v;
        }
    }
}

// ---------------------------------------------------------------------------
// Split-K narrow GEMM: partial[kc] = U[:, kc*256:(kc+1)*256] @ W_x[same rows]
// Grid (128 m-blocks, 8 k-chunks).  Then deterministic reduce.
// ---------------------------------------------------------------------------
__global__ __launch_bounds__(256) void gemm_n96_partial(
    const float* __restrict__ A, const float* __restrict__ B,
    float* __restrict__ P)
{
    const int BK = 32, NN = 96, KC = 256;
    __shared__ float As[BK][32];
    __shared__ float Bs[BK][NN];

    const int m0 = blockIdx.x * 32;
    const int kc = blockIdx.y;
    const int kbeg = kc * KC;
    const int tid = threadIdx.x;
    const int tx = tid & 15;
    const int ty = tid >> 4;

    float acc[2][6];
#pragma unroll
    for (int r = 0; r < 2; r++)
#pragma unroll
        for (int j = 0; j < 6; j++) acc[r][j] = 0.f;

    for (int k0 = kbeg; k0 < kbeg + KC; k0 += BK) {
        {
            int row = tid >> 3;
            int cv  = (tid & 7) * 4;
            float4 a = *(const float4*)(A + (size_t)(m0 + row) * DINNER + k0 + cv);
            As[cv + 0][row] = a.x; As[cv + 1][row] = a.y;
            As[cv + 2][row] = a.z; As[cv + 3][row] = a.w;
        }
#pragma unroll
        for (int i = 0; i < 3; i++) {
            int idx  = tid + i * 256;
            int rowB = idx / 24;
            int cv   = (idx % 24) * 4;
            *(float4*)(&Bs[rowB][cv]) =
                *(const float4*)(B + (size_t)(k0 + rowB) * NN + cv);
        }
        __syncthreads();
#pragma unroll
        for (int k = 0; k < BK; k++) {
            float a0 = As[k][ty * 2];
            float a1 = As[k][ty * 2 + 1];
#pragma unroll
            for (int j = 0; j < 6; j++) {
                float bb = Bs[k][tx * 6 + j];
                acc[0][j] = fmaf(a0, bb, acc[0][j]);
                acc[1][j] = fmaf(a1, bb, acc[1][j]);
            }
        }
        __syncthreads();
    }
    float* out = P + (size_t)kc * BLROWS * 96;
#pragma unroll
    for (int r = 0; r < 2; r++) {
        int m = m0 + ty * 2 + r;
#pragma unroll
        for (int j = 0; j < 6; j++)
            out[(size_t)m * 96 + tx * 6 + j] = acc[r][j];
    }
}

// Deterministic fixed-order reduction of 8 partials -> dbc
__global__ __launch_bounds__(256) void gemm_n96_reduce(
    const float* __restrict__ P, float* __restrict__ C)
{
    size_t i = ((size_t)blockIdx.x * blockDim.x + threadIdx.x) * 4;
    const size_t S = (size_t)BLROWS * 96;
    float4 s = *(const float4*)(P + i);
#pragma unroll
    for (int kc = 1; kc < 8; kc++) {
        float4 v = *(const float4*)(P + kc * S + i);
        s.x += v.x; s.y += v.y; s.z += v.z; s.w += v.w;
    }
    *(float4*)(C + i) = s;
}

// ---------------------------------------------------------------------------
// Selective scan with fused gate: y = (scan + u*D) * silu(res)  (fp32)
// ---------------------------------------------------------------------------
__global__ __launch_bounds__(256) void scan_kernel(
    const float* __restrict__ delta, const float* __restrict__ u,
    const float* __restrict__ dbc, const float* __restrict__ A_log,
    const float* __restrict__ Dp, const float* __restrict__ sres,
    float* __restrict__ Y)
{
    int tid = blockIdx.x * blockDim.x + threadIdx.x;
    int n = tid & 15;
    int d = (tid >> 4) & (DINNER - 1);
    int b = tid >> 15;

    const float a  = -__expf(A_log[d * DSTATE + n]);
    const float Dd = Dp[d];

    const size_t rowbase = (size_t)b * LSEQ;
    const float* dptr = delta + rowbase * DINNER + d;
    const float* uptr = u     + rowbase * DINNER + d;
    const float* bc   = dbc   + rowbase * 96;
    const float* rp   = sres  + rowbase * DINNER + d;
    float*       yp   = Y     + rowbase * DINNER + d;

    float h = 0.f;
    for (int t = 0; t < LSEQ; t++) {
        float de = dptr[(size_t)t * DINNER];
        float uu = uptr[(size_t)t * DINNER];
        float Bn = bc[t * 96 + DTRANK + n];
        float Cn = bc[t * 96 + DTRANK + DSTATE + n];
        float dA = __expf(de * a);
        h = fmaf(dA, h, de * uu * Bn);
        float p = h * Cn;
        p += __shfl_xor_sync(0xffffffffu, p, 8);
        p += __shfl_xor_sync(0xffffffffu, p, 4);
        p += __shfl_xor_sync(0xffffffffu, p, 2);
        p += __shfl_xor_sync(0xffffffffu, p, 1);
        if (n == 0)
            yp[(size_t)t * DINNER] = fmaf(uu, Dd, p) * rp[(size_t)t * DINNER];
    }
}

// ---------------------------------------------------------------------------
// Launch
// ---------------------------------------------------------------------------
extern "C" void kernel_launch(void* const* d_in, const int* in_sizes, int n_in,
                              void* d_out, int out_size)
{
    (void)in_sizes; (void)n_in; (void)out_size;
    const float* x      = (const float*)d_in[0];
    const float* W_in   = (const float*)d_in[1];
    const float* conv_k = (const float*)d_in[2];
    const float* conv_b = (const float*)d_in[3];
    const float* W_x    = (const float*)d_in[4];
    const float* W_dt   = (const float*)d_in[5];
    const float* b_dt   = (const float*)d_in[6];
    const float* A_log  = (const float*)d_in[7];
    const float* Dvec   = (const float*)d_in[8];
    const float* W_out  = (const float*)d_in[9];
    float* out = (float*)d_out;

    bf16 *xsh, *xsl, *convTh, *convTl;
    float *sres, *u, *dbc, *dbcp, *delta, *y, *winT, *woutT, *wdtT;
    cudaGetSymbolAddress((void**)&xsh,   g_xsh);
    cudaGetSymbolAddress((void**)&xsl,   g_xsl);
    cudaGetSymbolAddress((void**)&sres,  g_sres);
    cudaGetSymbolAddress((void**)&u,     g_u);
    cudaGetSymbolAddress((void**)&dbc,   g_dbc);
    cudaGetSymbolAddress((void**)&dbcp,  g_dbc_part);
    cudaGetSymbolAddress((void**)&delta, g_delta);
    cudaGetSymbolAddress((void**)&y,     g_y);
    cudaGetSymbolAddress((void**)&winT,  g_WinT);
    cudaGetSymbolAddress((void**)&convTh, g_convTh);
    cudaGetSymbolAddress((void**)&convTl, g_convTl);
    cudaGetSymbolAddress((void**)&woutT, g_WoutT);
    cudaGetSymbolAddress((void**)&wdtT,  g_WdtT);

    cudaFuncSetAttribute(conv_halo, cudaFuncAttributeMaxDynamicSharedMemorySize, CONV_SMEM);

    // 0) all weight preprocessing in ONE launch
    fused_transpose<<<dim3(128, 64, 7), dim3(32, 8)>>>(
        W_in, conv_k, W_out, W_dt, winT, convTh, convTl, woutT, wdtT);

    // 1) GEMM1: xs -> bf16 hi/lo,  silu(res) -> sres fp32
    mma_gemm<3><<<dim3(32, 32), 256>>>(
        x, DMODEL, winT, DMODEL, sres, DINNER, DMODEL, nullptr, xsh, xsl);

    // 2) halo-fused grouped causal conv + bias + silu -> u fp32
    conv_halo<<<dim3(16, 32), 256, CONV_SMEM>>>(
        xsh, xsl, convTh, convTl, conv_b, u);

    // 3) dbc = u @ W_x  (split-K 8x + deterministic reduce)
    gemm_n96_partial<<<dim3(128, 8), 256>>>(u, W_x, dbcp);
    gemm_n96_reduce<<<(BLROWS * 96 / 4) / 256, 256>>>(dbcp, dbc);

    // 4) delta = clip(softplus(dt_raw @ W_dt + b_dt))
    mma_gemm<1><<<dim3(16, 32), 256>>>(
        dbc, 96, wdtT, DTRANK, delta, DINNER, DTRANK, b_dt, nullptr, nullptr);

    // 5) selective scan + fused gate -> y fp32
    scan_kernel<<<256, 256>>>(delta, u, dbc, A_log, Dvec, sres, y);

    // 6) out = y @ W_out
    mma_gemm<0><<<dim3(8, 32), 256>>>(
        y, DINNER, woutT, DINNER, out, DMODEL, DINNER, nullptr, nullptr, nullptr);
}